// round 2
// baseline (speedup 1.0000x reference)
#include <cuda_runtime.h>
#include <math.h>

#define B_ 64
#define S_ 1024
#define D_ 512
#define H_ 1024
#define NCTA 128
#define NTHR 256
#define KC 64
#define SA_STR 68
#define SB_STR 33
#define SG_STR 66

typedef unsigned long long u64t;

// ---- persistent device state (scratch via __device__ globals: allowed) ----
__device__ float g_h0[2][H_][B_];   // layer-0 hidden, double buffered, [H][B]
__device__ float g_h1[2][H_][B_];   // layer-1 hidden, double buffered
__device__ unsigned g_bar_count;    // self-resetting arrival counter
__device__ unsigned g_bar_gen;      // monotonic generation (across graph replays)

// ---- helpers ---------------------------------------------------------------
__device__ __forceinline__ u64t pack2(float x, float y) {
    u64t r; asm("mov.b64 %0, {%1,%2};" : "=l"(r) : "f"(x), "f"(y)); return r;
}
__device__ __forceinline__ void unpack2(u64t v, float& x, float& y) {
    asm("mov.b64 {%0,%1}, %2;" : "=f"(x), "=f"(y) : "l"(v));
}
// packed fp32x2 FMA (FFMA2): d = a*b + d  -- 2x fp32 throughput on sm_103a
__device__ __forceinline__ void fma2(u64t& d, u64t a, u64t b) {
    asm("fma.rn.f32x2 %0, %1, %2, %0;" : "+l"(d) : "l"(a), "l"(b));
}
__device__ __forceinline__ float sig_(float v) { return 1.0f / (1.0f + __expf(-v)); }

// ---- grid barrier (all 128 CTAs resident: 128 <= 148 SMs) ------------------
__device__ __forceinline__ void grid_barrier(unsigned& gen) {
    __syncthreads();
    if (threadIdx.x == 0) {
        __threadfence();
        unsigned target = gen + 1u;
        if (atomicAdd(&g_bar_count, 1u) == NCTA - 1) {
            atomicExch(&g_bar_count, 0u);
            __threadfence();
            atomicAdd(&g_bar_gen, 1u);
        } else {
            while (*(volatile unsigned*)&g_bar_gen < target) { }
        }
        __threadfence();
    }
    gen++;
    __syncthreads();
}

// ---- staging: global -> registers -> shared --------------------------------
// h-layout source [K][B_] (k-major): straight vectorized copy
__device__ __forceinline__ void ldA_h(float4 pa[4], const float* __restrict__ src,
                                      int c, int tid) {
#pragma unroll
    for (int j = 0; j < 4; j++) {
        int idx = tid + j * NTHR, kk = idx >> 4, b4 = (idx & 15) * 4;
        pa[j] = *reinterpret_cast<const float4*>(src + (c * KC + kk) * B_ + b4);
    }
}
__device__ __forceinline__ void stA_h(const float4 pa[4], float* sa, int tid) {
#pragma unroll
    for (int j = 0; j < 4; j++) {
        int idx = tid + j * NTHR, kk = idx >> 4, b4 = (idx & 15) * 4;
        *reinterpret_cast<float4*>(sa + kk * SA_STR + b4) = pa[j];
    }
}
// x source x[b][t][d]: load along d, transpose into sa[d_local][b]
__device__ __forceinline__ void ldA_x(float4 pa[4], const float* __restrict__ src,
                                      int c, int tid) {
#pragma unroll
    for (int j = 0; j < 4; j++) {
        int idx = tid + j * NTHR, b = idx >> 4, dq = (idx & 15) * 4;
        pa[j] = *reinterpret_cast<const float4*>(src + (size_t)b * (S_ * D_) + c * KC + dq);
    }
}
__device__ __forceinline__ void stA_x(const float4 pa[4], float* sa, int tid) {
#pragma unroll
    for (int j = 0; j < 4; j++) {
        int idx = tid + j * NTHR, b = idx >> 4, dq = (idx & 15) * 4;
        sa[(dq + 0) * SA_STR + b] = pa[j].x;
        sa[(dq + 1) * SA_STR + b] = pa[j].y;
        sa[(dq + 2) * SA_STR + b] = pa[j].z;
        sa[(dq + 3) * SA_STR + b] = pa[j].w;
    }
}
// weights W[grow][Kdim] row-major: load along K, transpose into sb[k][g]
__device__ __forceinline__ void ldW(float4 pw[2], const float* __restrict__ W,
                                    int Kdim, int j0, int c, int tid) {
#pragma unroll
    for (int j = 0; j < 2; j++) {
        int idx = tid + j * NTHR, r = idx >> 4, kq = (idx & 15) * 4;
        int grow = (r >> 3) * H_ + j0 + (r & 7);
        pw[j] = *reinterpret_cast<const float4*>(W + (size_t)grow * Kdim + c * KC + kq);
    }
}
__device__ __forceinline__ void stW(const float4 pw[2], float* sb, int tid) {
#pragma unroll
    for (int j = 0; j < 2; j++) {
        int idx = tid + j * NTHR, r = idx >> 4, kq = (idx & 15) * 4;
        sb[(kq + 0) * SB_STR + r] = pw[j].x;
        sb[(kq + 1) * SB_STR + r] = pw[j].y;
        sb[(kq + 2) * SB_STR + r] = pw[j].z;
        sb[(kq + 3) * SB_STR + r] = pw[j].w;
    }
}

// ---- FFMA2 inner product over one staged K chunk ---------------------------
__device__ __forceinline__ void compute_chunk(const float* sa, const float* sb,
                                              int g, int bgrp, u64t acc[4]) {
    const float* ap = sa + bgrp * 8;   // warp-uniform -> broadcast LDS
    const float* wp = sb + g;          // lane-strided  -> conflict-free LDS
#pragma unroll
    for (int kk = 0; kk < KC; kk++) {
        float w = wp[kk * SB_STR];
        u64t wpk = pack2(w, w);
        const ulonglong2* av = reinterpret_cast<const ulonglong2*>(ap + kk * SA_STR);
        ulonglong2 a01 = av[0];
        ulonglong2 a23 = av[1];
        fma2(acc[0], a01.x, wpk);
        fma2(acc[1], a01.y, wpk);
        fma2(acc[2], a23.x, wpk);
        fma2(acc[3], a23.y, wpk);
    }
}

// one GEMM segment; XM: 1 = x-source (transpose), 0 = h-source
template <int XM>
__device__ __forceinline__ void gemm_part(u64t acc[4], const float* __restrict__ src,
                                          const float* __restrict__ W, int Kdim,
                                          int nch, int tid, int j0, int g, int bgrp,
                                          float* sa, float* sb) {
    float4 pa[4]; float4 pw[2];
    if (XM) ldA_x(pa, src, 0, tid); else ldA_h(pa, src, 0, tid);
    ldW(pw, W, Kdim, j0, 0, tid);
    for (int c = 0; c < nch; c++) {
        __syncthreads();                 // prior chunk compute done -> smem free
        if (XM) stA_x(pa, sa, tid); else stA_h(pa, sa, tid);
        stW(pw, sb, tid);
        __syncthreads();
        if (c + 1 < nch) {               // prefetch next chunk under compute
            if (XM) ldA_x(pa, src, c + 1, tid); else ldA_h(pa, src, c + 1, tid);
            ldW(pw, W, Kdim, j0, c + 1, tid);
        }
        compute_chunk(sa, sb, g, bgrp, acc);
    }
}

// ---- LSTM cell for one (unit, batch) ---------------------------------------
__device__ __forceinline__ float cellup(const float* sg, int uu, int b, float& cst) {
    float gi = sg[(0 + uu) * SG_STR + b];
    float gf = sg[(8 + uu) * SG_STR + b];
    float gg = sg[(16 + uu) * SG_STR + b];
    float go = sg[(24 + uu) * SG_STR + b];
    float cn = sig_(gf) * cst + sig_(gi) * tanhf(gg);
    cst = cn;
    return sig_(go) * tanhf(cn);
}

// ---- persistent kernel ------------------------------------------------------
__global__ void __launch_bounds__(NTHR, 1) lstm_persistent_kernel(
    const float* __restrict__ x,
    const float* __restrict__ Wih0, const float* __restrict__ Whh0,
    const float* __restrict__ bih0, const float* __restrict__ bhh0,
    const float* __restrict__ Wih1, const float* __restrict__ Whh1,
    const float* __restrict__ bih1, const float* __restrict__ bhh1,
    float* __restrict__ out) {
    __shared__ float sa[KC * SA_STR];
    __shared__ float sb[KC * SB_STR];
    __shared__ float sg[32 * SG_STR];

    const int tid = threadIdx.x;
    const int j0 = blockIdx.x * 8;      // first hidden unit owned by this CTA
    const int g = tid & 31;             // gate row within CTA tile
    const int bgrp = tid >> 5;          // batch group (8 batches)
    const int cb = tid >> 2;            // cell-update: batch
    const int cu = 2 * (tid & 3);       // cell-update: unit pair base

    const int grow = (g >> 3) * H_ + j0 + (g & 7);
    const float bias0 = bih0[grow] + bhh0[grow];
    const float bias1 = bih1[grow] + bhh1[grow];

    float c0a = 0.f, c0b = 0.f, c1a = 0.f, c1b = 0.f;

    float* coutp = out + (size_t)B_ * S_ * H_;
    float* h1f = out + 2ull * B_ * S_ * H_;
    float* c1f = h1f + (size_t)B_ * H_;

    // read generation BEFORE first arrival: stable (no barrier completes early)
    unsigned gen = *(volatile unsigned*)&g_bar_gen;

    // zero own slice of initial hidden buffers
    for (int i = tid; i < 8 * B_; i += NTHR) {
        g_h0[0][j0 + (i >> 6)][i & 63] = 0.f;
        g_h1[0][j0 + (i >> 6)][i & 63] = 0.f;
    }
    grid_barrier(gen);

    for (int t = 0; t < S_; t++) {
        const int rb = t & 1, wb = (t + 1) & 1;

        // ======== layer 0: gates = x_t@Wih0^T + h0@Whh0^T + b =========
        {
            u64t acc[4];
            u64t bp = pack2(bias0, bias0);
            acc[0] = bp; acc[1] = bp; acc[2] = bp; acc[3] = bp;
            gemm_part<1>(acc, x + (size_t)t * D_, Wih0, D_, D_ / KC,
                         tid, j0, g, bgrp, sa, sb);
            gemm_part<0>(acc, &g_h0[rb][0][0], Whh0, H_, H_ / KC,
                         tid, j0, g, bgrp, sa, sb);
            float v0, v1;
#pragma unroll
            for (int i = 0; i < 4; i++) {
                unpack2(acc[i], v0, v1);
                sg[g * SG_STR + bgrp * 8 + 2 * i] = v0;
                sg[g * SG_STR + bgrp * 8 + 2 * i + 1] = v1;
            }
            __syncthreads();
            float h0a = cellup(sg, cu, cb, c0a);
            float h0b = cellup(sg, cu + 1, cb, c0b);
            g_h0[wb][j0 + cu][cb] = h0a;
            g_h0[wb][j0 + cu + 1][cb] = h0b;
        }

        grid_barrier(gen);   // all h0(t) published

        // ======== layer 1: gates = h0_new@Wih1^T + h1@Whh1^T + b ========
        {
            u64t acc[4];
            u64t bp = pack2(bias1, bias1);
            acc[0] = bp; acc[1] = bp; acc[2] = bp; acc[3] = bp;
            const float* s1[2] = { &g_h0[wb][0][0], &g_h1[rb][0][0] };
            const float* w1[2] = { Wih1, Whh1 };
#pragma unroll 1
            for (int p = 0; p < 2; p++)
                gemm_part<0>(acc, s1[p], w1[p], H_, H_ / KC,
                             tid, j0, g, bgrp, sa, sb);
            float v0, v1;
#pragma unroll
            for (int i = 0; i < 4; i++) {
                unpack2(acc[i], v0, v1);
                sg[g * SG_STR + bgrp * 8 + 2 * i] = v0;
                sg[g * SG_STR + bgrp * 8 + 2 * i + 1] = v1;
            }
            __syncthreads();
            float h1a = cellup(sg, cu, cb, c1a);
            float h1b = cellup(sg, cu + 1, cb, c1b);
            g_h1[wb][j0 + cu][cb] = h1a;
            g_h1[wb][j0 + cu + 1][cb] = h1b;
            size_t ob = (size_t)cb * (S_ * H_) + (size_t)t * H_ + (j0 + cu);
            *reinterpret_cast<float2*>(out + ob) = make_float2(h1a, h1b);
            *reinterpret_cast<float2*>(coutp + ob) = make_float2(c1a, c1b);
            if (t == S_ - 1) {
                *reinterpret_cast<float2*>(h1f + cb * H_ + j0 + cu) = make_float2(h1a, h1b);
                *reinterpret_cast<float2*>(c1f + cb * H_ + j0 + cu) = make_float2(c1a, c1b);
            }
        }
        // no barrier needed here (double buffers absorb the 1-phase skew)
    }
}

extern "C" void kernel_launch(void* const* d_in, const int* in_sizes, int n_in,
                              void* d_out, int out_size) {
    const float* x    = (const float*)d_in[0];
    const float* Wih0 = (const float*)d_in[1];
    const float* Whh0 = (const float*)d_in[2];
    const float* bih0 = (const float*)d_in[3];
    const float* bhh0 = (const float*)d_in[4];
    const float* Wih1 = (const float*)d_in[5];
    const float* Whh1 = (const float*)d_in[6];
    const float* bih1 = (const float*)d_in[7];
    const float* bhh1 = (const float*)d_in[8];
    float* out = (float*)d_out;
    lstm_persistent_kernel<<<NCTA, NTHR>>>(x, Wih0, Whh0, bih0, bhh0,
                                           Wih1, Whh1, bih1, bhh1, out);
}

// round 3
// speedup vs baseline: 1.0672x; 1.0672x over previous
#include <cuda_runtime.h>
#include <math.h>

#define B_ 64
#define S_ 1024
#define D_ 512
#define H_ 1024
#define NCTA 128
#define NTHR 512
#define HALF 256
#define KC 32
#define SA_STR 68
#define SB_STR 33
#define SG_STR 66

typedef unsigned long long u64t;

// ---- persistent device state ----------------------------------------------
__device__ float g_h0[2][H_][B_];
__device__ float g_h1[2][H_][B_];
__device__ unsigned g_bar_count;
__device__ unsigned g_bar_gen;

// ---- helpers ---------------------------------------------------------------
__device__ __forceinline__ u64t pack2(float x, float y) {
    u64t r; asm("mov.b64 %0, {%1,%2};" : "=l"(r) : "f"(x), "f"(y)); return r;
}
__device__ __forceinline__ void unpack2(u64t v, float& x, float& y) {
    asm("mov.b64 {%0,%1}, %2;" : "=f"(x), "=f"(y) : "l"(v));
}
__device__ __forceinline__ void fma2(u64t& d, u64t a, u64t b) {
    asm("fma.rn.f32x2 %0, %1, %2, %0;" : "+l"(d) : "l"(a), "l"(b));
}
__device__ __forceinline__ float sig_(float v) { return 1.0f / (1.0f + __expf(-v)); }
// named barrier for one 256-thread half (ids 1 and 2; 0 is __syncthreads)
__device__ __forceinline__ void half_sync(int m) {
    asm volatile("bar.sync %0, %1;" :: "r"(m + 1), "r"(HALF) : "memory");
}

// ---- grid barrier (128 CTAs, all resident) ---------------------------------
__device__ __forceinline__ void grid_barrier(unsigned& gen) {
    __syncthreads();
    if (threadIdx.x == 0) {
        __threadfence();
        unsigned target = gen + 1u;
        if (atomicAdd(&g_bar_count, 1u) == NCTA - 1) {
            atomicExch(&g_bar_count, 0u);
            __threadfence();
            atomicAdd(&g_bar_gen, 1u);
        } else {
            while (*(volatile unsigned*)&g_bar_gen < target) { }
        }
        __threadfence();
    }
    gen++;
    __syncthreads();
}

// ---- staging (per half: 256 threads, chunk = 32 K x 64 B / 32 K x 32 G) ----
__device__ __forceinline__ void ldA_h(float4 pa[2], const float* __restrict__ src,
                                      int kbase, int t2) {
#pragma unroll
    for (int j = 0; j < 2; j++) {
        int idx = t2 + j * HALF, kk = idx >> 4, b4 = (idx & 15) * 4;
        pa[j] = *reinterpret_cast<const float4*>(src + (kbase + kk) * B_ + b4);
    }
}
__device__ __forceinline__ void stA_h(const float4 pa[2], float* sa, int t2) {
#pragma unroll
    for (int j = 0; j < 2; j++) {
        int idx = t2 + j * HALF, kk = idx >> 4, b4 = (idx & 15) * 4;
        *reinterpret_cast<float4*>(sa + kk * SA_STR + b4) = pa[j];
    }
}
__device__ __forceinline__ void ldA_x(float4 pa[2], const float* __restrict__ xt,
                                      int kbase, int t2) {
#pragma unroll
    for (int j = 0; j < 2; j++) {
        int idx = t2 + j * HALF, b = idx >> 3, dq = (idx & 7) * 4;
        pa[j] = *reinterpret_cast<const float4*>(xt + (size_t)b * (S_ * D_) + kbase + dq);
    }
}
__device__ __forceinline__ void stA_x(const float4 pa[2], float* sa, int t2) {
#pragma unroll
    for (int j = 0; j < 2; j++) {
        int idx = t2 + j * HALF, b = idx >> 3, dq = (idx & 7) * 4;
        sa[(dq + 0) * SA_STR + b] = pa[j].x;
        sa[(dq + 1) * SA_STR + b] = pa[j].y;
        sa[(dq + 2) * SA_STR + b] = pa[j].z;
        sa[(dq + 3) * SA_STR + b] = pa[j].w;
    }
}
__device__ __forceinline__ void ldW(float4 pw[1], const float* __restrict__ W,
                                    int Kdim, int j0, int kbase, int t2) {
    int r = t2 >> 3, kq = (t2 & 7) * 4;
    int grow = (r >> 3) * H_ + j0 + (r & 7);
    pw[0] = *reinterpret_cast<const float4*>(W + (size_t)grow * Kdim + kbase + kq);
}
__device__ __forceinline__ void stW(const float4 pw[1], float* sb, int t2) {
    int r = t2 >> 3, kq = (t2 & 7) * 4;
    sb[(kq + 0) * SB_STR + r] = pw[0].x;
    sb[(kq + 1) * SB_STR + r] = pw[0].y;
    sb[(kq + 2) * SB_STR + r] = pw[0].z;
    sb[(kq + 3) * SB_STR + r] = pw[0].w;
}

// ---- FFMA2 inner product over one staged chunk ------------------------------
__device__ __forceinline__ void compute_chunk(const float* sa, const float* sb,
                                              int g, int bgrp, u64t acc[4]) {
    const float* ap = sa + bgrp * 8;
    const float* wp = sb + g;
#pragma unroll 8
    for (int kk = 0; kk < KC; kk++) {
        float w = wp[kk * SB_STR];
        u64t wpk = pack2(w, w);
        const ulonglong2* av = reinterpret_cast<const ulonglong2*>(ap + kk * SA_STR);
        ulonglong2 a01 = av[0];
        ulonglong2 a23 = av[1];
        fma2(acc[0], a01.x, wpk);
        fma2(acc[1], a01.y, wpk);
        fma2(acc[2], a23.x, wpk);
        fma2(acc[3], a23.y, wpk);
    }
}

// one GEMM segment over this half's K range [k0, k0 + nch*KC)
// XM: 1 = x-source (transpose), 0 = h-source [K][B]
template <int XM>
__device__ __forceinline__ void gemm_part(u64t acc[4], const float* __restrict__ src,
                                          const float* __restrict__ W, int Kdim,
                                          int k0, int nch, int t2, int m, int j0,
                                          int g, int bgrp, float* sa, float* sb) {
    float4 pa[2]; float4 pw[1];
    if (XM) ldA_x(pa, src, k0, t2); else ldA_h(pa, src, k0, t2);
    ldW(pw, W, Kdim, j0, k0, t2);
    for (int c = 0; c < nch; c++) {
        half_sync(m);                    // prior chunk compute done
        if (XM) stA_x(pa, sa, t2); else stA_h(pa, sa, t2);
        stW(pw, sb, t2);
        half_sync(m);
        if (c + 1 < nch) {
            int kb = k0 + (c + 1) * KC;
            if (XM) ldA_x(pa, src, kb, t2); else ldA_h(pa, src, kb, t2);
            ldW(pw, W, Kdim, j0, kb, t2);
        }
        compute_chunk(sa, sb, g, bgrp, acc);
    }
}

__device__ __forceinline__ void scatter_gates(const u64t acc[4], float* sg,
                                              int g, int bgrp) {
    float v0, v1;
#pragma unroll
    for (int i = 0; i < 4; i++) {
        unpack2(acc[i], v0, v1);
        sg[g * SG_STR + bgrp * 8 + 2 * i] = v0;
        sg[g * SG_STR + bgrp * 8 + 2 * i + 1] = v1;
    }
}

// ---- persistent kernel ------------------------------------------------------
__global__ void __launch_bounds__(NTHR, 1) lstm_persistent_kernel(
    const float* __restrict__ x,
    const float* __restrict__ Wih0, const float* __restrict__ Whh0,
    const float* __restrict__ bih0, const float* __restrict__ bhh0,
    const float* __restrict__ Wih1, const float* __restrict__ Whh1,
    const float* __restrict__ bih1, const float* __restrict__ bhh1,
    float* __restrict__ out) {
    __shared__ float sa[2][KC * SA_STR];
    __shared__ float sb[2][KC * SB_STR];
    __shared__ float sg[2][32 * SG_STR];

    const int tid = threadIdx.x;
    const int m = tid >> 8;             // half index (K-split)
    const int t2 = tid & (HALF - 1);    // thread id within half
    const int j0 = blockIdx.x * 8;      // first hidden unit owned by CTA
    const int g = t2 & 31;              // gate row within CTA tile
    const int bgrp = t2 >> 5;           // batch group of 8
    const int cb = tid >> 3;            // cell-update: batch (0..63)
    const int cu = tid & 7;             // cell-update: unit (0..7)

    const int grow = (g >> 3) * H_ + j0 + (g & 7);
    const float bias0 = (m == 0) ? (bih0[grow] + bhh0[grow]) : 0.f;
    const float bias1 = (m == 0) ? (bih1[grow] + bhh1[grow]) : 0.f;

    float c0 = 0.f, c1 = 0.f;           // cell states for (cb, j0+cu)

    float* coutp = out + (size_t)B_ * S_ * H_;
    float* h1f = out + 2ull * B_ * S_ * H_;
    float* c1f = h1f + (size_t)B_ * H_;

    unsigned gen = *(volatile unsigned*)&g_bar_gen;

    // zero own slice of initial hidden buffers (512 threads, 512 elements)
    g_h0[0][j0 + cu][cb] = 0.f;
    g_h1[0][j0 + cu][cb] = 0.f;
    grid_barrier(gen);

    for (int t = 0; t < S_; t++) {
        const int rb = t & 1, wb = (t + 1) & 1;

        // ======== layer 0: gates = x_t@Wih0^T + h0@Whh0^T + b ========
        {
            u64t acc[4];
            u64t bp = pack2(bias0, bias0);
            acc[0] = bp; acc[1] = bp; acc[2] = bp; acc[3] = bp;
            gemm_part<1>(acc, x + (size_t)t * D_, Wih0, D_, m * (D_ / 2),
                         (D_ / 2) / KC, t2, m, j0, g, bgrp, sa[m], sb[m]);
            gemm_part<0>(acc, &g_h0[rb][0][0], Whh0, H_, m * (H_ / 2),
                         (H_ / 2) / KC, t2, m, j0, g, bgrp, sa[m], sb[m]);
            scatter_gates(acc, sg[m], g, bgrp);
            __syncthreads();
            // cell update: one (batch, unit) per thread; merge half partials
            float gi = sg[0][(0 + cu) * SG_STR + cb] + sg[1][(0 + cu) * SG_STR + cb];
            float gf = sg[0][(8 + cu) * SG_STR + cb] + sg[1][(8 + cu) * SG_STR + cb];
            float gg = sg[0][(16 + cu) * SG_STR + cb] + sg[1][(16 + cu) * SG_STR + cb];
            float go = sg[0][(24 + cu) * SG_STR + cb] + sg[1][(24 + cu) * SG_STR + cb];
            float cn = sig_(gf) * c0 + sig_(gi) * tanhf(gg);
            c0 = cn;
            g_h0[wb][j0 + cu][cb] = sig_(go) * tanhf(cn);
        }

        grid_barrier(gen);   // all h0(t) published (also protects sg reuse)

        // ======== layer 1: gates = h0_new@Wih1^T + h1@Whh1^T + b ========
        {
            u64t acc[4];
            u64t bp = pack2(bias1, bias1);
            acc[0] = bp; acc[1] = bp; acc[2] = bp; acc[3] = bp;
            gemm_part<0>(acc, &g_h0[wb][0][0], Wih1, H_, m * (H_ / 2),
                         (H_ / 2) / KC, t2, m, j0, g, bgrp, sa[m], sb[m]);
            gemm_part<0>(acc, &g_h1[rb][0][0], Whh1, H_, m * (H_ / 2),
                         (H_ / 2) / KC, t2, m, j0, g, bgrp, sa[m], sb[m]);
            scatter_gates(acc, sg[m], g, bgrp);
            __syncthreads();
            float gi = sg[0][(0 + cu) * SG_STR + cb] + sg[1][(0 + cu) * SG_STR + cb];
            float gf = sg[0][(8 + cu) * SG_STR + cb] + sg[1][(8 + cu) * SG_STR + cb];
            float gg = sg[0][(16 + cu) * SG_STR + cb] + sg[1][(16 + cu) * SG_STR + cb];
            float go = sg[0][(24 + cu) * SG_STR + cb] + sg[1][(24 + cu) * SG_STR + cb];
            float cn = sig_(gf) * c1 + sig_(gi) * tanhf(gg);
            c1 = cn;
            float hn = sig_(go) * tanhf(cn);
            g_h1[wb][j0 + cu][cb] = hn;
            size_t ob = (size_t)cb * (S_ * H_) + (size_t)t * H_ + (j0 + cu);
            out[ob] = hn;
            coutp[ob] = cn;
            if (t == S_ - 1) {
                h1f[cb * H_ + j0 + cu] = hn;
                c1f[cb * H_ + j0 + cu] = cn;
            }
        }
        __syncthreads();     // sg readers done before next step's writers
    }
}

extern "C" void kernel_launch(void* const* d_in, const int* in_sizes, int n_in,
                              void* d_out, int out_size) {
    const float* x    = (const float*)d_in[0];
    const float* Wih0 = (const float*)d_in[1];
    const float* Whh0 = (const float*)d_in[2];
    const float* bih0 = (const float*)d_in[3];
    const float* bhh0 = (const float*)d_in[4];
    const float* Wih1 = (const float*)d_in[5];
    const float* Whh1 = (const float*)d_in[6];
    const float* bih1 = (const float*)d_in[7];
    const float* bhh1 = (const float*)d_in[8];
    float* out = (float*)d_out;
    lstm_persistent_kernel<<<NCTA, NTHR>>>(x, Wih0, Whh0, bih0, bhh0,
                                           Wih1, Whh1, bih1, bhh1, out);
}